// round 1
// baseline (speedup 1.0000x reference)
#include <cuda_runtime.h>
#include <math.h>
#include <stdint.h>

#define Bz 8192
#define Tz 10
#define Fz 561
#define Hz 256
#define Oz 12
#define Gz (4*Hz)   // 1024

// ---------------- scratch (static device globals; no runtime alloc) ----------
__device__ float g_xp[(size_t)Bz*Tz*Hz];        // [B*T, H]
__device__ float g_A0[(size_t)Bz*Tz*Gz];        // [T, B, 4H] (permuted)
__device__ float g_gates0[(size_t)Bz*Gz];
__device__ float g_gates1[(size_t)Bz*Gz];
__device__ float g_h0[Bz*Hz], g_c0[Bz*Hz], g_h1[Bz*Hz], g_c1[Bz*Hz];
__device__ float g_hs[(size_t)Tz*Bz*Hz];        // [T, B, H]
__device__ float g_bias0[Gz], g_bias1[Gz];

// ---------------- generic SGEMM: C[m,n] = base + sum_k A[m,k]*W[n,k] ---------
// base = Cin[m,n] if Cin, else bias[n] if bias, else 0.  (C may alias Cin.)
// If permT: output row remap m=(b*T+t) -> t*B+b  (N must be mult of 64)
#define BM 64
#define BN 64
#define BK 16

__global__ __launch_bounds__(256) void gemm_kernel(
    float* __restrict__ C, const float* __restrict__ Cin,
    const float* __restrict__ bias,
    const float* __restrict__ A, const float* __restrict__ W,
    int M, int N, int K, int permT)
{
    __shared__ float As[BK][BM];
    __shared__ float Ws[BK][BN];

    int m0 = blockIdx.x * BM;
    int n0 = blockIdx.y * BN;
    int tid = threadIdx.x;
    int tx = tid & 15;        // 0..15 -> 4 cols each
    int ty = tid >> 4;        // 0..15 -> 4 rows each

    float acc[4][4];
#pragma unroll
    for (int i = 0; i < 4; i++)
#pragma unroll
        for (int j = 0; j < 4; j++) acc[i][j] = 0.f;

    for (int k0 = 0; k0 < K; k0 += BK) {
        // load A tile (64x16), 4 elems/thread, k fastest for coalescing
#pragma unroll
        for (int r = 0; r < 4; r++) {
            int idx = tid + r * 256;
            int i = idx >> 4;
            int k = idx & 15;
            int gm = m0 + i, gk = k0 + k;
            As[k][i] = (gm < M && gk < K) ? A[(size_t)gm * K + gk] : 0.f;
        }
        // load W tile: Ws[k][n] = W[n0+n][k0+k]
#pragma unroll
        for (int r = 0; r < 4; r++) {
            int idx = tid + r * 256;
            int n = idx >> 4;
            int k = idx & 15;
            int gk = k0 + k;
            Ws[k][n] = (gk < K) ? W[(size_t)(n0 + n) * K + gk] : 0.f;
        }
        __syncthreads();

#pragma unroll
        for (int k = 0; k < BK; k++) {
            float4 ra = *reinterpret_cast<const float4*>(&As[k][ty * 4]);
            float4 rb = *reinterpret_cast<const float4*>(&Ws[k][tx * 4]);
            float a4[4] = {ra.x, ra.y, ra.z, ra.w};
            float b4[4] = {rb.x, rb.y, rb.z, rb.w};
#pragma unroll
            for (int i = 0; i < 4; i++)
#pragma unroll
                for (int j = 0; j < 4; j++)
                    acc[i][j] += a4[i] * b4[j];
        }
        __syncthreads();
    }

#pragma unroll
    for (int i = 0; i < 4; i++) {
        int m = m0 + ty * 4 + i;
        if (m >= M) continue;
        size_t row = permT ? ((size_t)(m % Tz) * Bz + (m / Tz)) : (size_t)m;
#pragma unroll
        for (int j = 0; j < 4; j++) {
            int n = n0 + tx * 4 + j;
            float base = Cin ? Cin[row * N + n] : (bias ? bias[n] : 0.f);
            C[row * N + n] = base + acc[i][j];
        }
    }
}

// ---------------- LSTM cell elementwise ----------------
__device__ __forceinline__ float sigm(float x) { return 1.f / (1.f + expf(-x)); }

__global__ void lstm_cell_kernel(const float* __restrict__ gates,
                                 float* __restrict__ h, float* __restrict__ c,
                                 float* __restrict__ hs_slice)
{
    int idx = blockIdx.x * blockDim.x + threadIdx.x;
    if (idx >= Bz * Hz) return;
    int b = idx / Hz, j = idx % Hz;
    const float* g = gates + (size_t)b * Gz;
    float ig = sigm(g[j]);
    float fg = sigm(g[Hz + j]);
    float gg = tanhf(g[2 * Hz + j]);
    float og = sigm(g[3 * Hz + j]);
    float cn = fg * c[idx] + ig * gg;
    float hn = og * tanhf(cn);
    c[idx] = cn;
    h[idx] = hn;
    if (hs_slice) hs_slice[idx] = hn;
}

// ---------------- init: zero h/c, combine biases ----------------
__global__ void init_kernel(const float* bih0, const float* bhh0,
                            const float* bih1, const float* bhh1)
{
    int idx = blockIdx.x * blockDim.x + threadIdx.x;
    if (idx < Gz) {
        g_bias0[idx] = bih0[idx] + bhh0[idx];
        g_bias1[idx] = bih1[idx] + bhh1[idx];
    }
    for (int i = idx; i < Bz * Hz; i += gridDim.x * blockDim.x) {
        g_h0[i] = 0.f; g_c0[i] = 0.f; g_h1[i] = 0.f; g_c1[i] = 0.f;
    }
}

// ---------------- output projection: warp per (t,b) row ----------------
__global__ __launch_bounds__(256) void out_kernel(
    const float* __restrict__ hs, const float* __restrict__ Wout,
    const float* __restrict__ bout, float* __restrict__ out)
{
    __shared__ float Ws[Oz * Hz];
    for (int i = threadIdx.x; i < Oz * Hz; i += blockDim.x) Ws[i] = Wout[i];
    __syncthreads();
    int warp = (blockIdx.x * blockDim.x + threadIdx.x) >> 5;
    int lane = threadIdx.x & 31;
    if (warp >= Tz * Bz) return;
    int t = warp / Bz, b = warp % Bz;
    const float* hrow = hs + ((size_t)t * Bz + b) * Hz;
    float hv[8];
#pragma unroll
    for (int i = 0; i < 8; i++) hv[i] = hrow[lane + 32 * i];
    float* orow = out + ((size_t)b * Tz + t) * Oz;
#pragma unroll
    for (int o = 0; o < Oz; o++) {
        float s = 0.f;
#pragma unroll
        for (int i = 0; i < 8; i++) s += hv[i] * Ws[o * Hz + lane + 32 * i];
#pragma unroll
        for (int off = 16; off; off >>= 1) s += __shfl_down_sync(0xffffffffu, s, off);
        if (lane == 0) orow[o] = s + bout[o];
    }
}

// ---------------- finalize: write h_n, c_n ----------------
__global__ void finalize_kernel(float* __restrict__ out)
{
    size_t OUT0 = (size_t)Bz * Tz * Oz;
    int idx = blockIdx.x * blockDim.x + threadIdx.x;
    int n = Bz * Hz;
    if (idx >= 2 * n) return;
    // h_n [2,B,H] then c_n [2,B,H]
    const float* hsrc = (idx < n) ? g_h0 : g_h1;
    const float* csrc = (idx < n) ? g_c0 : g_c1;
    int off = (idx < n) ? idx : idx - n;
    out[OUT0 + idx] = hsrc[off];
    out[OUT0 + 2 * (size_t)n + idx] = csrc[off];
}

// ---------------- host launcher ----------------
extern "C" void kernel_launch(void* const* d_in, const int* in_sizes, int n_in,
                              void* d_out, int out_size)
{
    const float* inputs = (const float*)d_in[0];
    const float* W_inp  = (const float*)d_in[1];
    const float* b_inp  = (const float*)d_in[2];
    const float* Wih0   = (const float*)d_in[3];
    const float* Whh0   = (const float*)d_in[4];
    const float* bih0   = (const float*)d_in[5];
    const float* bhh0   = (const float*)d_in[6];
    const float* Wih1   = (const float*)d_in[7];
    const float* Whh1   = (const float*)d_in[8];
    const float* bih1   = (const float*)d_in[9];
    const float* bhh1   = (const float*)d_in[10];
    const float* W_out  = (const float*)d_in[11];
    const float* b_out  = (const float*)d_in[12];
    float* out = (float*)d_out;

    void *p_xp, *p_A0, *p_g0, *p_g1, *p_h0, *p_c0, *p_h1, *p_c1, *p_hs, *p_b0, *p_b1;
    cudaGetSymbolAddress(&p_xp, g_xp);
    cudaGetSymbolAddress(&p_A0, g_A0);
    cudaGetSymbolAddress(&p_g0, g_gates0);
    cudaGetSymbolAddress(&p_g1, g_gates1);
    cudaGetSymbolAddress(&p_h0, g_h0);
    cudaGetSymbolAddress(&p_c0, g_c0);
    cudaGetSymbolAddress(&p_h1, g_h1);
    cudaGetSymbolAddress(&p_c1, g_c1);
    cudaGetSymbolAddress(&p_hs, g_hs);
    cudaGetSymbolAddress(&p_b0, g_bias0);
    cudaGetSymbolAddress(&p_b1, g_bias1);
    float* xp = (float*)p_xp;  float* A0 = (float*)p_A0;
    float* gg0 = (float*)p_g0; float* gg1 = (float*)p_g1;
    float* h0 = (float*)p_h0;  float* c0 = (float*)p_c0;
    float* h1 = (float*)p_h1;  float* c1 = (float*)p_c1;
    float* hs = (float*)p_hs;
    float* bias0 = (float*)p_b0; float* bias1 = (float*)p_b1;

    // init h/c + combined biases
    init_kernel<<<1024, 256>>>(bih0, bhh0, bih1, bhh1);

    const int MT = Bz * Tz;   // 81920

    // xp = inputs @ W_inp^T + b_inp            [B*T, H]
    {
        dim3 grid((MT + BM - 1) / BM, Hz / BN);
        gemm_kernel<<<grid, 256>>>(xp, nullptr, b_inp, inputs, W_inp, MT, Hz, Fz, 0);
    }
    // A0 = xp @ Wih0^T + (bih0+bhh0), permuted to [T, B, 4H]
    {
        dim3 grid((MT + BM - 1) / BM, Gz / BN);
        gemm_kernel<<<grid, 256>>>(A0, nullptr, bias0, xp, Wih0, MT, Gz, Hz, 1);
    }

    dim3 gridS((Bz + BM - 1) / BM, Gz / BN);
    int cellBlocks = (Bz * Hz + 255) / 256;

    for (int t = 0; t < Tz; t++) {
        // layer0: gates0 = A0[t] + h0 @ Whh0^T
        gemm_kernel<<<gridS, 256>>>(gg0, A0 + (size_t)t * Bz * Gz, nullptr,
                                    h0, Whh0, Bz, Gz, Hz, 0);
        lstm_cell_kernel<<<cellBlocks, 256>>>(gg0, h0, c0, nullptr);

        // layer1: gates1 = bias1 + h0_new @ Wih1^T + h1_prev @ Whh1^T
        gemm_kernel<<<gridS, 256>>>(gg1, nullptr, bias1, h0, Wih1, Bz, Gz, Hz, 0);
        gemm_kernel<<<gridS, 256>>>(gg1, gg1, nullptr, h1, Whh1, Bz, Gz, Hz, 0);
        lstm_cell_kernel<<<cellBlocks, 256>>>(gg1, h1, c1, hs + (size_t)t * Bz * Hz);
    }

    // outputs = hs @ W_out^T + b_out   (warp per (t,b))
    {
        int warps = Tz * Bz;
        int blocks = (warps * 32 + 255) / 256;
        out_kernel<<<blocks, 256>>>(hs, W_out, b_out, out);
    }
    // h_n, c_n
    finalize_kernel<<<(2 * Bz * Hz + 255) / 256, 256>>>(out);
}

// round 3
// speedup vs baseline: 2.2536x; 2.2536x over previous
#include <cuda_runtime.h>
#include <math.h>
#include <stdint.h>

#define Bz 8192
#define Tz 10
#define Fz 561
#define Hz 256
#define Oz 12
#define Gz 1024   // 4*H

// ---------------- scratch ----------------
__device__ float g_xp[(size_t)Bz*Tz*Hz];        // [B*T, H]
__device__ float g_A0[(size_t)Bz*Tz*Gz];        // [T, B, 4H] gate-interleaved
__device__ float g_h0[2][Bz*Hz];
__device__ float g_h1[2][Bz*Hz];
__device__ float g_c0[Bz*Hz], g_c1[Bz*Hz];
__device__ float g_hs[(size_t)Tz*Bz*Hz];        // [T, B, H]
__device__ float g_Wih0r[Gz*Hz];                // gate-interleaved rows
__device__ float g_Whh0r[Gz*Hz];
__device__ float g_W1cat[Gz*2*Hz];              // [1024][512] = [Wih1 | Whh1] interleaved
__device__ float g_bias0[Gz], g_bias1[Gz];      // interleaved combined biases

// ---------------- tiled f32x2 SGEMM ----------------
#define BM 128
#define BN 128
#define BK 16
#define PAD 132

__device__ __forceinline__ float sigm(float x) { return 1.f / (1.f + expf(-x)); }

// C[m,n] = base + sum_k A[m,k] * W[n,k]
// base = (Cin ? Cin[m*NT+n] : 0) + (bias ? bias[n] : 0)
// MODE 0: store C[m][n]
// MODE 1: store C with row remap m=(b*T+t) -> t*B + b   (A0 build)
// MODE 2: LSTM cell epilogue (gate-interleaved N): reads/writes cst, writes hout (+hsout)
template<int MODE, int NT>
__global__ __launch_bounds__(256, 2) void gemm_f32x2(
    float* __restrict__ C, const float* __restrict__ Cin,
    const float* __restrict__ bias,
    const float* __restrict__ A1, int lda1, int K1,
    const float* __restrict__ A2, int lda2, int K2,
    const float* __restrict__ W, int ldw,
    float* __restrict__ cst, float* __restrict__ hout, float* __restrict__ hsout,
    int M)
{
    __shared__ float As[BK][PAD];
    __shared__ float Ws[BK][PAD];

    const int m0 = blockIdx.x * BM;
    const int n0 = blockIdx.y * BN;
    const int tid = threadIdx.x;
    const int tx = tid & 15;
    const int ty = tid >> 4;

    unsigned long long acc[8][4];
#pragma unroll
    for (int r = 0; r < 8; r++)
#pragma unroll
        for (int q = 0; q < 4; q++) acc[r][q] = 0ull;

    int wo = 0;
#pragma unroll 1
    for (int seg = 0; seg < 2; seg++) {
        const float* A = (seg == 0) ? A1 : A2;
        const int lda  = (seg == 0) ? lda1 : lda2;
        const int K    = (seg == 0) ? K1 : K2;
        if (A == nullptr || K == 0) break;

        for (int k0 = 0; k0 < K; k0 += BK) {
            const bool fullA = ((lda & 3) == 0) && (k0 + BK <= K);
            const bool fullW = ((ldw & 3) == 0) && (k0 + BK <= K);

            // ---- load A tile (BM x BK) -> As[k][m] ----
#pragma unroll
            for (int r = 0; r < 2; r++) {
                int f = tid + r * 256;
                int row = f >> 2;
                int kq = (f & 3) * 4;
                const float* src = A + (size_t)(m0 + row) * lda + k0 + kq;
                if (fullA) {
                    float4 v = *reinterpret_cast<const float4*>(src);
                    As[kq + 0][row] = v.x; As[kq + 1][row] = v.y;
                    As[kq + 2][row] = v.z; As[kq + 3][row] = v.w;
                } else {
#pragma unroll
                    for (int i = 0; i < 4; i++) {
                        int gk = k0 + kq + i;
                        As[kq + i][row] = (gk < K) ? src[i] : 0.f;
                    }
                }
            }
            // ---- load W tile (BN x BK) -> Ws[k][n] ----
#pragma unroll
            for (int r = 0; r < 2; r++) {
                int f = tid + r * 256;
                int row = f >> 2;
                int kq = (f & 3) * 4;
                const float* src = W + (size_t)(n0 + row) * ldw + wo + k0 + kq;
                if (fullW) {
                    float4 v = *reinterpret_cast<const float4*>(src);
                    Ws[kq + 0][row] = v.x; Ws[kq + 1][row] = v.y;
                    Ws[kq + 2][row] = v.z; Ws[kq + 3][row] = v.w;
                } else {
#pragma unroll
                    for (int i = 0; i < 4; i++) {
                        int gk = k0 + kq + i;
                        Ws[kq + i][row] = (gk < K) ? src[i] : 0.f;
                    }
                }
            }
            __syncthreads();

            // ---- mainloop: packed f32x2 FMAs ----
#pragma unroll
            for (int k = 0; k < BK; k++) {
                float4 ra0 = *reinterpret_cast<const float4*>(&As[k][ty * 4]);
                float4 ra1 = *reinterpret_cast<const float4*>(&As[k][ty * 4 + 64]);
                ulonglong2 b01 = *reinterpret_cast<const ulonglong2*>(&Ws[k][tx * 4]);
                ulonglong2 b23 = *reinterpret_cast<const ulonglong2*>(&Ws[k][tx * 4 + 64]);
                unsigned long long pb0 = b01.x, pb1 = b01.y, pb2 = b23.x, pb3 = b23.y;
                float av[8] = {ra0.x, ra0.y, ra0.z, ra0.w, ra1.x, ra1.y, ra1.z, ra1.w};
#pragma unroll
                for (int r = 0; r < 8; r++) {
                    unsigned long long pa;
                    asm("mov.b64 %0, {%1, %1};" : "=l"(pa) : "r"(__float_as_uint(av[r])));
                    asm("fma.rn.f32x2 %0, %1, %2, %0;" : "+l"(acc[r][0]) : "l"(pa), "l"(pb0));
                    asm("fma.rn.f32x2 %0, %1, %2, %0;" : "+l"(acc[r][1]) : "l"(pa), "l"(pb1));
                    asm("fma.rn.f32x2 %0, %1, %2, %0;" : "+l"(acc[r][2]) : "l"(pa), "l"(pb2));
                    asm("fma.rn.f32x2 %0, %1, %2, %0;" : "+l"(acc[r][3]) : "l"(pa), "l"(pb3));
                }
            }
            __syncthreads();
        }
        wo += K;
    }

    // ---- epilogue ----
#pragma unroll
    for (int r = 0; r < 8; r++) {
        int m = m0 + ty * 4 + (r < 4 ? r : 60 + r);  // ty*4 + r  or  ty*4+64+(r-4)
#pragma unroll
        for (int half = 0; half < 2; half++) {
            int n = n0 + tx * 4 + half * 64;
            union { unsigned long long u; float2 f; } c0v, c1v;
            c0v.u = acc[r][half * 2 + 0];
            c1v.u = acc[r][half * 2 + 1];
            float4 g4 = make_float4(c0v.f.x, c0v.f.y, c1v.f.x, c1v.f.y);
            if (Cin) {
                float4 cb = *reinterpret_cast<const float4*>(&Cin[(size_t)m * NT + n]);
                g4.x += cb.x; g4.y += cb.y; g4.z += cb.z; g4.w += cb.w;
            }
            if (bias) {
                float4 bb = *reinterpret_cast<const float4*>(&bias[n]);
                g4.x += bb.x; g4.y += bb.y; g4.z += bb.z; g4.w += bb.w;
            }
            if (MODE == 2) {
                // gate-interleaved: n..n+3 = (i,f,g,o) for j = n/4
                float ig = sigm(g4.x);
                float fg = sigm(g4.y);
                float gg = tanhf(g4.z);
                float og = sigm(g4.w);
                int ci = m * Hz + (n >> 2);
                float cn = fg * cst[ci] + ig * gg;
                float hn = og * tanhf(cn);
                cst[ci] = cn;
                hout[ci] = hn;
                if (hsout) hsout[ci] = hn;
            } else {
                size_t row = (MODE == 1)
                    ? ((size_t)(m % Tz) * (size_t)(M / Tz) + (size_t)(m / Tz))
                    : (size_t)m;
                *reinterpret_cast<float4*>(&C[row * NT + n]) = g4;
            }
        }
    }
}

// ---------------- init: reorder weights, combine biases, zero state ----------
__global__ void init_kernel(const float* __restrict__ bih0, const float* __restrict__ bhh0,
                            const float* __restrict__ bih1, const float* __restrict__ bhh1,
                            const float* __restrict__ Wih0, const float* __restrict__ Whh0,
                            const float* __restrict__ Wih1, const float* __restrict__ Whh1)
{
    int idx = blockIdx.x * blockDim.x + threadIdx.x;
    int stride = gridDim.x * blockDim.x;
    for (int i = idx; i < Gz * Hz; i += stride) {
        int nr = i / Hz, k = i % Hz;
        int old = (nr & 3) * Hz + (nr >> 2);   // new row j*4+g <- old row g*H+j
        g_Wih0r[i] = Wih0[old * Hz + k];
        g_Whh0r[i] = Whh0[old * Hz + k];
        g_W1cat[(size_t)nr * 512 + k]       = Wih1[old * Hz + k];
        g_W1cat[(size_t)nr * 512 + 256 + k] = Whh1[old * Hz + k];
    }
    for (int i = idx; i < Gz; i += stride) {
        int old = (i & 3) * Hz + (i >> 2);
        g_bias0[i] = bih0[old] + bhh0[old];
        g_bias1[i] = bih1[old] + bhh1[old];
    }
    for (int i = idx; i < Bz * Hz; i += stride) {
        g_h0[0][i] = 0.f; g_h1[0][i] = 0.f;
        g_c0[i] = 0.f; g_c1[i] = 0.f;
    }
}

// ---------------- output projection: warp per (t,b) row ----------------
__global__ __launch_bounds__(256) void out_kernel(
    const float* __restrict__ hs, const float* __restrict__ Wout,
    const float* __restrict__ bout, float* __restrict__ out)
{
    __shared__ float Ws[Oz * Hz];
    for (int i = threadIdx.x; i < Oz * Hz; i += blockDim.x) Ws[i] = Wout[i];
    __syncthreads();
    int warp = (blockIdx.x * blockDim.x + threadIdx.x) >> 5;
    int lane = threadIdx.x & 31;
    if (warp >= Tz * Bz) return;
    int t = warp / Bz, b = warp % Bz;
    const float* hrow = hs + ((size_t)t * Bz + b) * Hz;
    float hv[8];
#pragma unroll
    for (int i = 0; i < 8; i++) hv[i] = hrow[lane + 32 * i];
    float* orow = out + ((size_t)b * Tz + t) * Oz;
#pragma unroll
    for (int o = 0; o < Oz; o++) {
        float s = 0.f;
#pragma unroll
        for (int i = 0; i < 8; i++) s += hv[i] * Ws[o * Hz + lane + 32 * i];
#pragma unroll
        for (int off = 16; off; off >>= 1) s += __shfl_down_sync(0xffffffffu, s, off);
        if (lane == 0) orow[o] = s + bout[o];
    }
}

// ---------------- finalize: h_n, c_n ----------------
__global__ void finalize_kernel(float* __restrict__ out)
{
    size_t OUT0 = (size_t)Bz * Tz * Oz;
    int idx = blockIdx.x * blockDim.x + threadIdx.x;
    int n = Bz * Hz;
    if (idx >= 2 * n) return;
    // final state lives in buffer index T%2 == 0
    const float* hsrc = (idx < n) ? g_h0[0] : g_h1[0];
    const float* csrc = (idx < n) ? g_c0 : g_c1;
    int off = (idx < n) ? idx : idx - n;
    out[OUT0 + idx] = hsrc[off];
    out[OUT0 + 2 * (size_t)n + idx] = csrc[off];
}

// ---------------- host launcher ----------------
extern "C" void kernel_launch(void* const* d_in, const int* in_sizes, int n_in,
                              void* d_out, int out_size)
{
    const float* inputs = (const float*)d_in[0];
    const float* W_inp  = (const float*)d_in[1];
    const float* b_inp  = (const float*)d_in[2];
    const float* Wih0   = (const float*)d_in[3];
    const float* Whh0   = (const float*)d_in[4];
    const float* bih0   = (const float*)d_in[5];
    const float* bhh0   = (const float*)d_in[6];
    const float* Wih1   = (const float*)d_in[7];
    const float* Whh1   = (const float*)d_in[8];
    const float* bih1   = (const float*)d_in[9];
    const float* bhh1   = (const float*)d_in[10];
    const float* W_out  = (const float*)d_in[11];
    const float* b_out  = (const float*)d_in[12];
    float* out = (float*)d_out;

    void *p;
    cudaGetSymbolAddress(&p, g_xp);    float* xp = (float*)p;
    cudaGetSymbolAddress(&p, g_A0);    float* A0 = (float*)p;
    cudaGetSymbolAddress(&p, g_h0);    float* h0b = (float*)p;   // [2][B*H]
    cudaGetSymbolAddress(&p, g_h1);    float* h1b = (float*)p;
    cudaGetSymbolAddress(&p, g_c0);    float* c0 = (float*)p;
    cudaGetSymbolAddress(&p, g_c1);    float* c1 = (float*)p;
    cudaGetSymbolAddress(&p, g_hs);    float* hs = (float*)p;
    cudaGetSymbolAddress(&p, g_Wih0r); float* Wih0r = (float*)p;
    cudaGetSymbolAddress(&p, g_Whh0r); float* Whh0r = (float*)p;
    cudaGetSymbolAddress(&p, g_W1cat); float* W1cat = (float*)p;
    cudaGetSymbolAddress(&p, g_bias0); float* bias0 = (float*)p;
    cudaGetSymbolAddress(&p, g_bias1); float* bias1 = (float*)p;

    const int MT = Bz * Tz;   // 81920
    const int BH = Bz * Hz;

    init_kernel<<<512, 256>>>(bih0, bhh0, bih1, bhh1, Wih0, Whh0, Wih1, Whh1);

    // xp = inputs @ W_inp^T + b_inp     [B*T, 256]
    gemm_f32x2<0, 256><<<dim3(MT / BM, 2), 256>>>(
        xp, nullptr, b_inp,
        inputs, Fz, Fz, nullptr, 0, 0,
        W_inp, Fz, nullptr, nullptr, nullptr, MT);

    // A0 = xp @ Wih0r^T + bias0, permuted to [T, B, 1024] (gate-interleaved)
    gemm_f32x2<1, 1024><<<dim3(MT / BM, 8), 256>>>(
        A0, nullptr, bias0,
        xp, Hz, Hz, nullptr, 0, 0,
        Wih0r, Hz, nullptr, nullptr, nullptr, MT);

    for (int t = 0; t < Tz; t++) {
        int pp = t & 1;
        // layer0: gates = A0[t] + h0 @ Whh0r^T ; fused cell -> h0[1-p], c0
        gemm_f32x2<2, 1024><<<dim3(Bz / BM, 8), 256>>>(
            nullptr, A0 + (size_t)t * Bz * Gz, nullptr,
            h0b + (size_t)pp * BH, Hz, Hz, nullptr, 0, 0,
            Whh0r, Hz, c0, h0b + (size_t)(1 - pp) * BH, nullptr, Bz);
        // layer1: gates = bias1 + h0_new @ Wih1^T + h1 @ Whh1^T ; fused cell
        gemm_f32x2<2, 1024><<<dim3(Bz / BM, 8), 256>>>(
            nullptr, nullptr, bias1,
            h0b + (size_t)(1 - pp) * BH, Hz, Hz,
            h1b + (size_t)pp * BH, Hz, Hz,
            W1cat, 2 * Hz, c1, h1b + (size_t)(1 - pp) * BH,
            hs + (size_t)t * Bz * Hz, Bz);
    }

    // outputs = hs @ W_out^T + b_out
    {
        int warps = Tz * Bz;
        int blocks = (warps * 32 + 255) / 256;
        out_kernel<<<blocks, 256>>>(hs, W_out, b_out, out);
    }
    finalize_kernel<<<(2 * BH + 255) / 256, 256>>>(out);
}